// round 3
// baseline (speedup 1.0000x reference)
#include <cuda_runtime.h>

// CRF loss: logZ - gold.  T=512, B=512, N=64.
// Exp-space forward recurrence with lagged power-of-2 renormalization.

#define TT 512
#define BB 512
#define NN 64
#define LOG2E 1.4426950408889634f
#define LN2F  0.6931471805599453f
#define STRIDE_F (BB * NN)              // floats per t-slice

#define FWD_BLOCKS  128
#define GOLD_BLOCKS 2048                 // (T*B)/128
#define TOT_BLOCKS  (FWD_BLOCKS + GOLD_BLOCKS)

__device__ __align__(16) float g_EpT[NN * NN];   // exp(trans)^T : [j][i]
__device__ int      g_len[BB];
__device__ double   g_logZ;
__device__ double   g_gold;
__device__ unsigned g_done;

__device__ __forceinline__ float ex2f_(float x) {
    float y; asm("ex2.approx.ftz.f32 %0, %1;" : "=f"(y) : "f"(x)); return y;
}
__device__ __forceinline__ float lg2f_(float x) {
    float y; asm("lg2.approx.ftz.f32 %0, %1;" : "=f"(y) : "f"(x)); return y;
}
__device__ __forceinline__ void fma2_(unsigned long long& d,
                                      unsigned long long a,
                                      unsigned long long b) {
    asm("fma.rn.f32x2 %0, %1, %2, %0;" : "+l"(d) : "l"(a), "l"(b));
}
__device__ __forceinline__ unsigned long long add2_(unsigned long long a,
                                                    unsigned long long b) {
    unsigned long long d;
    asm("add.rn.f32x2 %0, %1, %2;" : "=l"(d) : "l"(a), "l"(b));
    return d;
}
__device__ __forceinline__ float pairsum_(unsigned long long a) {
    unsigned lo, hi;
    asm("mov.b64 {%0, %1}, %2;" : "=r"(lo), "=r"(hi) : "l"(a));
    return __uint_as_float(lo) + __uint_as_float(hi);
}
__device__ __forceinline__ unsigned long long packf2_(float a, float b) {
    unsigned long long r;
    asm("mov.b64 %0, {%1, %2};" : "=l"(r) : "f"(a), "f"(b));
    return r;
}

// mask dtype: 0=int32, 1=float32, 2=byte  (row t=0 is all-true since lengths>=1)
__device__ __forceinline__ int mask_kind(const void* maskp) {
    unsigned w0 = ((const unsigned*)maskp)[0];
    return (w0 == 1u) ? 0 : (w0 == 0x3F800000u ? 1 : 2);
}
__device__ __forceinline__ bool mask_at(const void* maskp, int kind, int idx) {
    if (kind == 0) return ((const int*)maskp)[idx] != 0;
    if (kind == 1) return ((const float*)maskp)[idx] != 0.0f;
    return ((const unsigned char*)maskp)[idx] != 0;
}

// ---------------- init ------------------------------------------------------
__global__ void k_init(const float* __restrict__ trans, const void* __restrict__ maskp) {
    int tid = blockIdx.x * blockDim.x + threadIdx.x;
    if (tid < NN * NN) {
        int i = tid & (NN - 1);
        int j = tid >> 6;
        g_EpT[tid] = ex2f_(LOG2E * trans[i * NN + j]);
    }
    int b = tid - NN * NN;
    if (b >= 0 && b < BB) {
        int kind = mask_kind(maskp);
        int len = 0;
        for (int t = 0; t < TT; ++t) len += mask_at(maskp, kind, t * BB + b);
        g_len[b] = len;
    }
    if (tid == 0) { g_logZ = 0.0; g_gold = 0.0; g_done = 0u; }
}

// ---------------- fused forward + gold + final ------------------------------
__global__ void __launch_bounds__(128, 1)
k_main(const float* __restrict__ emit,
       const float* __restrict__ trans,
       const float* __restrict__ strans,
       const float* __restrict__ etrans,
       const int*   __restrict__ target,
       const void*  __restrict__ maskp,
       float*       __restrict__ out) {
    __shared__ unsigned long long pbuf[2][4][32];

    if (blockIdx.x < FWD_BLOCKS) {
        const int w = threadIdx.x >> 5;
        const int l = threadIdx.x & 31;
        const int b = blockIdx.x * 4 + w;

        ulonglong2 E0[16], E1[16];
        {
            const ulonglong2* ep0 = (const ulonglong2*)(g_EpT + (2 * l) * NN);
            const ulonglong2* ep1 = (const ulonglong2*)(g_EpT + (2 * l + 1) * NN);
#pragma unroll
            for (int k = 0; k < 16; ++k) { E0[k] = ep0[k]; E1[k] = ep1[k]; }
        }

        const int len = g_len[b];
        const float* eb = emit + (size_t)b * NN + 2 * l;

        // init: P_0 = 2^(A - M0), m = M0 (log2 units)
        float2 e0 = *(const float2*)eb;
        float2 st = *(const float2*)(strans + 2 * l);
        float A0 = LOG2E * (e0.x + st.x);
        float A1 = LOG2E * (e0.y + st.y);
        float M0 = __shfl_sync(0xffffffffu, A0, 0);
        float PF0 = ex2f_(A0 - M0);
        float PF1 = ex2f_(A1 - M0);
        float mlog = M0;
        float u = 1.0f;       // current scale 2^{-dcur}
        float dcur = 0.0f;

        pbuf[1][w][l] = packf2_(PF0, PF1);   // buffer read by step t=1
        __syncwarp();

        // g ring: g[t] = 2^(LOG2E * emit[t]), prefetched 4 steps ahead
        float2 gr0, gr1, gr2, gr3;
#define LOADG(var, tt) { int tc = (tt) < len ? (tt) : (len - 1);              \
        float2 ee = *(const float2*)(eb + (size_t)tc * STRIDE_F);             \
        var = make_float2(ex2f_(LOG2E * ee.x), ex2f_(LOG2E * ee.y)); }
        LOADG(gr0, 1) LOADG(gr1, 2) LOADG(gr2, 3) LOADG(gr3, 4)

        int t = 1;
        // BI: buffer holding P_{t-1}; BO: buffer for P_t (= BI^1)
#define BODY(GR, BI, BO) {                                                    \
        mlog += dcur;                                                         \
        float gux = GR.x * u;                                                 \
        float guy = GR.y * u;                                                 \
        const ulonglong2* pb = (const ulonglong2*)pbuf[BI][w];                \
        unsigned long long aA0 = 0, aA1 = 0, aA2 = 0, aA3 = 0;                \
        unsigned long long aB0 = 0, aB1 = 0, aB2 = 0, aB3 = 0;                \
        _Pragma("unroll")                                                     \
        for (int m = 0; m < 16; m += 2) {                                     \
            ulonglong2 q = pb[m];                                             \
            ulonglong2 r = pb[m + 1];                                         \
            fma2_(aA0, q.x, E0[m].x);     fma2_(aA1, q.y, E0[m].y);           \
            fma2_(aB0, q.x, E1[m].x);     fma2_(aB1, q.y, E1[m].y);           \
            fma2_(aA2, r.x, E0[m + 1].x); fma2_(aA3, r.y, E0[m + 1].y);       \
            fma2_(aB2, r.x, E1[m + 1].x); fma2_(aB3, r.y, E1[m + 1].y);       \
        }                                                                     \
        { int tc = (t + 4) < len ? (t + 4) : (len - 1);                       \
          float2 ee = *(const float2*)(eb + (size_t)tc * STRIDE_F);           \
          GR = make_float2(ex2f_(LOG2E * ee.x), ex2f_(LOG2E * ee.y)); }       \
        float s0 = pairsum_(add2_(add2_(aA0, aA1), add2_(aA2, aA3)));         \
        float s1 = pairsum_(add2_(add2_(aB0, aB1), add2_(aB2, aB3)));         \
        PF0 = s0 * gux; PF1 = s1 * guy;                                       \
        pbuf[BO][w][l] = packf2_(PF0, PF1);                                   \
        float v0b = __shfl_sync(0xffffffffu, s0, 0);                          \
        int ex = (int)((__float_as_uint(v0b) >> 23) & 0xFF);                  \
        int d = ex - 127;                                                     \
        if (ex == 0 || ex == 255) d = 0;                                      \
        if (d > 120) d = 120; if (d < -120) d = -120;                         \
        u = __uint_as_float((unsigned)(127 - d) << 23);                       \
        dcur = (float)d;                                                      \
        __syncwarp();                                                         \
        ++t; }

        while (t + 3 < len) {            // t ≡ 1 (mod 4) at loop head
            BODY(gr0, 1, 0)
            BODY(gr1, 0, 1)
            BODY(gr2, 1, 0)
            BODY(gr3, 0, 1)
        }
        while (t < len) {                // ≤3 remainder steps, g inline
            float2 ee = *(const float2*)(eb + (size_t)t * STRIDE_F);
            float2 gi = make_float2(ex2f_(LOG2E * ee.x), ex2f_(LOG2E * ee.y));
            int bi = t & 1, bo = bi ^ 1;
            mlog += dcur;
            float gux = gi.x * u, guy = gi.y * u;
            const ulonglong2* pb = (const ulonglong2*)pbuf[bi][w];
            unsigned long long aA0 = 0, aA1 = 0, aA2 = 0, aA3 = 0;
            unsigned long long aB0 = 0, aB1 = 0, aB2 = 0, aB3 = 0;
#pragma unroll
            for (int m = 0; m < 16; m += 2) {
                ulonglong2 q = pb[m];
                ulonglong2 r = pb[m + 1];
                fma2_(aA0, q.x, E0[m].x);     fma2_(aA1, q.y, E0[m].y);
                fma2_(aB0, q.x, E1[m].x);     fma2_(aB1, q.y, E1[m].y);
                fma2_(aA2, r.x, E0[m + 1].x); fma2_(aA3, r.y, E0[m + 1].y);
                fma2_(aB2, r.x, E1[m + 1].x); fma2_(aB3, r.y, E1[m + 1].y);
            }
            float s0 = pairsum_(add2_(add2_(aA0, aA1), add2_(aA2, aA3)));
            float s1 = pairsum_(add2_(add2_(aB0, aB1), add2_(aB2, aB3)));
            PF0 = s0 * gux; PF1 = s1 * guy;
            pbuf[bo][w][l] = packf2_(PF0, PF1);
            float v0b = __shfl_sync(0xffffffffu, s0, 0);
            int ex = (int)((__float_as_uint(v0b) >> 23) & 0xFF);
            int d = ex - 127;
            if (ex == 0 || ex == 255) d = 0;
            if (d > 120) d = 120; if (d < -120) d = -120;
            u = __uint_as_float((unsigned)(127 - d) << 23);
            dcur = (float)d;
            __syncwarp();
            ++t;
        }

        // alpha_j (log2) = lg2(PF) + mlog ; logZ_b = ln LSE(alpha + etrans)
        float2 et = *(const float2*)(etrans + 2 * l);
        float G0 = lg2f_(PF0) + mlog + LOG2E * et.x;
        float G1 = lg2f_(PF1) + mlog + LOG2E * et.y;
        float m2 = fmaxf(G0, G1);
#pragma unroll
        for (int o = 16; o; o >>= 1) m2 = fmaxf(m2, __shfl_xor_sync(0xffffffffu, m2, o));
        float s = ex2f_(G0 - m2) + ex2f_(G1 - m2);
#pragma unroll
        for (int o = 16; o; o >>= 1) s += __shfl_xor_sync(0xffffffffu, s, o);
        if (l == 0)
            atomicAdd(&g_logZ, (double)(LN2F * (m2 + lg2f_(s))));
    } else {
        // ======== gold path score ========
        int idx = (blockIdx.x - FWD_BLOCKS) * 128 + threadIdx.x;  // = t*BB + b
        int t = idx >> 9;
        int kind = mask_kind(maskp);
        float c = 0.0f;
        if (mask_at(maskp, kind, idx)) {
            int tg = target[idx];
            c = emit[(size_t)idx * NN + tg];
            if (t > 0) c += trans[target[idx - BB] * NN + tg];
            else       c += strans[tg];
            bool mnext = (t < TT - 1) && mask_at(maskp, kind, idx + BB);
            if (!mnext) c += etrans[tg];
        }
#pragma unroll
        for (int o = 16; o; o >>= 1) c += __shfl_xor_sync(0xffffffffu, c, o);
        if ((threadIdx.x & 31) == 0) atomicAdd(&g_gold, (double)c);
    }

    // ======== last block writes the result ========
    __syncthreads();
    if (threadIdx.x == 0) {
        __threadfence();
        if (atomicAdd(&g_done, 1u) == TOT_BLOCKS - 1) {
            double lz = atomicAdd(&g_logZ, 0.0);
            double gd = atomicAdd(&g_gold, 0.0);
            out[0] = (float)(lz - gd);
        }
    }
}

extern "C" void kernel_launch(void* const* d_in, const int* in_sizes, int n_in,
                              void* d_out, int out_size) {
    const float* emit   = (const float*)d_in[0];
    const float* trans  = (const float*)d_in[1];
    const float* strans = (const float*)d_in[2];
    const float* etrans = (const float*)d_in[3];
    const int*   target = (const int*)d_in[4];
    const void*  mask   = d_in[5];
    (void)in_sizes; (void)n_in; (void)out_size;

    k_init<<<18, 256>>>(trans, mask);
    k_main<<<TOT_BLOCKS, 128>>>(emit, trans, strans, etrans, target, mask,
                                (float*)d_out);
}

// round 4
// speedup vs baseline: 1.1043x; 1.1043x over previous
#include <cuda_runtime.h>

// CRF loss: logZ - gold.  T=512, B=512, N=64.
// Exp-space forward recurrence, lagged power-of-2 renorm, deep raw prefetch.

#define TT 512
#define BB 512
#define NN 64
#define LOG2E 1.4426950408889634f
#define LN2F  0.6931471805599453f
#define STRIDE_F (BB * NN)

#define FWD_BLOCKS  128
#define GOLD_BLOCKS 2048
#define TOT_BLOCKS  (FWD_BLOCKS + GOLD_BLOCKS)

__device__ __align__(16) float g_EpT[NN * NN];   // exp(trans)^T : [j][i]
__device__ double   g_logZ;
__device__ double   g_gold;
__device__ unsigned g_done;

__device__ __forceinline__ float ex2f_(float x) {
    float y; asm("ex2.approx.ftz.f32 %0, %1;" : "=f"(y) : "f"(x)); return y;
}
__device__ __forceinline__ float lg2f_(float x) {
    float y; asm("lg2.approx.ftz.f32 %0, %1;" : "=f"(y) : "f"(x)); return y;
}
__device__ __forceinline__ void fma2_(unsigned long long& d,
                                      unsigned long long a,
                                      unsigned long long b) {
    asm("fma.rn.f32x2 %0, %1, %2, %0;" : "+l"(d) : "l"(a), "l"(b));
}
__device__ __forceinline__ unsigned long long add2_(unsigned long long a,
                                                    unsigned long long b) {
    unsigned long long d;
    asm("add.rn.f32x2 %0, %1, %2;" : "=l"(d) : "l"(a), "l"(b));
    return d;
}
__device__ __forceinline__ float pairsum_(unsigned long long a) {
    unsigned lo, hi;
    asm("mov.b64 {%0, %1}, %2;" : "=r"(lo), "=r"(hi) : "l"(a));
    return __uint_as_float(lo) + __uint_as_float(hi);
}
__device__ __forceinline__ unsigned long long packf2_(float a, float b) {
    unsigned long long r;
    asm("mov.b64 %0, {%1, %2};" : "=l"(r) : "f"(a), "f"(b));
    return r;
}

// mask dtype: 0=int32, 1=float32, 2=byte  (row t=0 all-true since lengths>=1)
__device__ __forceinline__ int mask_kind(const void* maskp) {
    unsigned w0 = ((const unsigned*)maskp)[0];
    return (w0 == 1u) ? 0 : (w0 == 0x3F800000u ? 1 : 2);
}
__device__ __forceinline__ bool mask_at(const void* maskp, int kind, int idx) {
    if (kind == 0) return ((const int*)maskp)[idx] != 0;
    if (kind == 1) return ((const float*)maskp)[idx] != 0.0f;
    return ((const unsigned char*)maskp)[idx] != 0;
}

// ---------------- init: exp(trans)^T + zero accumulators --------------------
__global__ void k_init(const float* __restrict__ trans) {
    int tid = blockIdx.x * blockDim.x + threadIdx.x;
    if (tid < NN * NN) {
        int i = tid & (NN - 1);
        int j = tid >> 6;
        g_EpT[tid] = ex2f_(LOG2E * trans[i * NN + j]);
    }
    if (tid == 0) { g_logZ = 0.0; g_gold = 0.0; g_done = 0u; }
}

// ---------------- fused forward + gold + final ------------------------------
__global__ void __launch_bounds__(128, 1)
k_main(const float* __restrict__ emit,
       const float* __restrict__ trans,
       const float* __restrict__ strans,
       const float* __restrict__ etrans,
       const int*   __restrict__ target,
       const void*  __restrict__ maskp,
       float*       __restrict__ out) {
    __shared__ unsigned long long pbuf[2][4][32];

    if (blockIdx.x < FWD_BLOCKS) {
        const int w = threadIdx.x >> 5;
        const int l = threadIdx.x & 31;
        const int b = blockIdx.x * 4 + w;

        // warp computes its own chain length from the prefix mask
        const int kind = mask_kind(maskp);
        int cnt = 0;
#pragma unroll
        for (int k = 0; k < 16; ++k)
            cnt += mask_at(maskp, kind, (l + 32 * k) * BB + b) ? 1 : 0;
        const int len = __reduce_add_sync(0xffffffffu, cnt);

        // E columns for j = 2l, 2l+1, i-pair packed
        ulonglong2 E0[16], E1[16];
        {
            const ulonglong2* ep0 = (const ulonglong2*)(g_EpT + (2 * l) * NN);
            const ulonglong2* ep1 = (const ulonglong2*)(g_EpT + (2 * l + 1) * NN);
#pragma unroll
            for (int k = 0; k < 16; ++k) { E0[k] = ep0[k]; E1[k] = ep1[k]; }
        }

        const float* eb = emit + (size_t)b * NN + 2 * l;

        float2 e0 = *(const float2*)eb;
        float2 st = *(const float2*)(strans + 2 * l);
        float A0 = LOG2E * (e0.x + st.x);
        float A1 = LOG2E * (e0.y + st.y);
        float M0 = __shfl_sync(0xffffffffu, A0, 0);
        float PF0 = ex2f_(A0 - M0);
        float PF1 = ex2f_(A1 - M0);
        float mlog = M0;
        float u = 1.0f;
        float dcur = 0.0f;

        pbuf[1][w][l] = packf2_(PF0, PF1);
        __syncwarp();

        // raw emit ring, depth 4: load now, convert 4 bodies later
        float2 r0, r1, r2, r3;
#define LOADR(var, tt) { int tc = (tt) < len ? (tt) : (len - 1);              \
        var = *(const float2*)(eb + (size_t)tc * STRIDE_F); }
        LOADR(r0, 1) LOADR(r1, 2) LOADR(r2, 3) LOADR(r3, 4)

        int t = 1;
#define BODY(RR, BI, BO) {                                                    \
        mlog += dcur;                                                         \
        float gx = ex2f_(LOG2E * RR.x);   /* RR loaded 4 bodies ago */        \
        float gy = ex2f_(LOG2E * RR.y);                                       \
        { int tc = (t + 4) < len ? (t + 4) : (len - 1);                       \
          RR = *(const float2*)(eb + (size_t)tc * STRIDE_F); }                \
        const ulonglong2* pb = (const ulonglong2*)pbuf[BI][w];                \
        unsigned long long aA0 = 0, aA1 = 0, aA2 = 0, aA3 = 0;                \
        unsigned long long aB0 = 0, aB1 = 0, aB2 = 0, aB3 = 0;                \
        _Pragma("unroll")                                                     \
        for (int m = 0; m < 16; m += 2) {                                     \
            ulonglong2 q = pb[m];                                             \
            ulonglong2 r = pb[m + 1];                                         \
            fma2_(aA0, q.x, E0[m].x);     fma2_(aA1, q.y, E0[m].y);           \
            fma2_(aB0, q.x, E1[m].x);     fma2_(aB1, q.y, E1[m].y);           \
            fma2_(aA2, r.x, E0[m + 1].x); fma2_(aA3, r.y, E0[m + 1].y);       \
            fma2_(aB2, r.x, E1[m + 1].x); fma2_(aB3, r.y, E1[m + 1].y);       \
        }                                                                     \
        float gux = gx * u;                                                   \
        float guy = gy * u;                                                   \
        float s0 = pairsum_(add2_(add2_(aA0, aA1), add2_(aA2, aA3)));         \
        float s1 = pairsum_(add2_(add2_(aB0, aB1), add2_(aB2, aB3)));         \
        PF0 = s0 * gux; PF1 = s1 * guy;                                       \
        pbuf[BO][w][l] = packf2_(PF0, PF1);                                   \
        float v0b = __shfl_sync(0xffffffffu, s0, 0);                          \
        int ex = (int)((__float_as_uint(v0b) >> 23) & 0xFF);                  \
        int d = ex - 127;                                                     \
        if (ex == 0 || ex == 255) d = 0;                                      \
        if (d > 120) d = 120; if (d < -120) d = -120;                         \
        u = __uint_as_float((unsigned)(127 - d) << 23);                       \
        dcur = (float)d;                                                      \
        __syncwarp();                                                         \
        ++t; }

        while (t + 3 < len) {            // t ≡ 1 (mod 4) at loop head
            BODY(r0, 1, 0)
            BODY(r1, 0, 1)
            BODY(r2, 1, 0)
            BODY(r3, 0, 1)
        }
        while (t < len) {                // ≤3 remainder steps
            float2 rr = *(const float2*)(eb + (size_t)t * STRIDE_F);
            int bi = t & 1, bo = bi ^ 1;
            mlog += dcur;
            float gx = ex2f_(LOG2E * rr.x);
            float gy = ex2f_(LOG2E * rr.y);
            const ulonglong2* pb = (const ulonglong2*)pbuf[bi][w];
            unsigned long long aA0 = 0, aA1 = 0, aA2 = 0, aA3 = 0;
            unsigned long long aB0 = 0, aB1 = 0, aB2 = 0, aB3 = 0;
#pragma unroll
            for (int m = 0; m < 16; m += 2) {
                ulonglong2 q = pb[m];
                ulonglong2 r = pb[m + 1];
                fma2_(aA0, q.x, E0[m].x);     fma2_(aA1, q.y, E0[m].y);
                fma2_(aB0, q.x, E1[m].x);     fma2_(aB1, q.y, E1[m].y);
                fma2_(aA2, r.x, E0[m + 1].x); fma2_(aA3, r.y, E0[m + 1].y);
                fma2_(aB2, r.x, E1[m + 1].x); fma2_(aB3, r.y, E1[m + 1].y);
            }
            float gux = gx * u, guy = gy * u;
            float s0 = pairsum_(add2_(add2_(aA0, aA1), add2_(aA2, aA3)));
            float s1 = pairsum_(add2_(add2_(aB0, aB1), add2_(aB2, aB3)));
            PF0 = s0 * gux; PF1 = s1 * guy;
            pbuf[bo][w][l] = packf2_(PF0, PF1);
            float v0b = __shfl_sync(0xffffffffu, s0, 0);
            int ex = (int)((__float_as_uint(v0b) >> 23) & 0xFF);
            int d = ex - 127;
            if (ex == 0 || ex == 255) d = 0;
            if (d > 120) d = 120; if (d < -120) d = -120;
            u = __uint_as_float((unsigned)(127 - d) << 23);
            dcur = (float)d;
            __syncwarp();
            ++t;
        }

        // logZ_b = ln LSE_j(alpha_j + etrans_j),  alpha(log2) = lg2(PF)+mlog
        float2 et = *(const float2*)(etrans + 2 * l);
        float G0 = lg2f_(PF0) + mlog + LOG2E * et.x;
        float G1 = lg2f_(PF1) + mlog + LOG2E * et.y;
        float m2 = fmaxf(G0, G1);
#pragma unroll
        for (int o = 16; o; o >>= 1) m2 = fmaxf(m2, __shfl_xor_sync(0xffffffffu, m2, o));
        float s = ex2f_(G0 - m2) + ex2f_(G1 - m2);
#pragma unroll
        for (int o = 16; o; o >>= 1) s += __shfl_xor_sync(0xffffffffu, s, o);
        if (l == 0)
            atomicAdd(&g_logZ, (double)(LN2F * (m2 + lg2f_(s))));
    } else {
        // ======== gold path score ========
        int idx = (blockIdx.x - FWD_BLOCKS) * 128 + threadIdx.x;  // = t*BB + b
        int t = idx >> 9;
        int kind = mask_kind(maskp);
        float c = 0.0f;
        if (mask_at(maskp, kind, idx)) {
            int tg = target[idx];
            c = emit[(size_t)idx * NN + tg];
            if (t > 0) c += trans[target[idx - BB] * NN + tg];
            else       c += strans[tg];
            bool mnext = (t < TT - 1) && mask_at(maskp, kind, idx + BB);
            if (!mnext) c += etrans[tg];
        }
#pragma unroll
        for (int o = 16; o; o >>= 1) c += __shfl_xor_sync(0xffffffffu, c, o);
        if ((threadIdx.x & 31) == 0) atomicAdd(&g_gold, (double)c);
    }

    // ======== last block writes the result ========
    __syncthreads();
    if (threadIdx.x == 0) {
        __threadfence();
        if (atomicAdd(&g_done, 1u) == TOT_BLOCKS - 1) {
            double lz = atomicAdd(&g_logZ, 0.0);
            double gd = atomicAdd(&g_gold, 0.0);
            out[0] = (float)(lz - gd);
        }
    }
}

extern "C" void kernel_launch(void* const* d_in, const int* in_sizes, int n_in,
                              void* d_out, int out_size) {
    const float* emit   = (const float*)d_in[0];
    const float* trans  = (const float*)d_in[1];
    const float* strans = (const float*)d_in[2];
    const float* etrans = (const float*)d_in[3];
    const int*   target = (const int*)d_in[4];
    const void*  mask   = d_in[5];
    (void)in_sizes; (void)n_in; (void)out_size;

    k_init<<<16, 256>>>(trans);
    k_main<<<TOT_BLOCKS, 128>>>(emit, trans, strans, etrans, target, mask,
                                (float*)d_out);
}

// round 5
// speedup vs baseline: 1.3467x; 1.2196x over previous
#include <cuda_runtime.h>

// CRF loss: logZ - gold.  T=512, B=512, N=64.
// Exp-space forward recurrence, 2 warps per chain (j-split), lagged pow2 renorm.

#define TT 512
#define BB 512
#define NN 64
#define LOG2E 1.4426950408889634f
#define LN2F  0.6931471805599453f
#define STRIDE_F (BB * NN)

#define FWD_BLOCKS  512                  // one chain per 64-thread block
#define GOLD_BLOCKS 4096                 // (T*B)/64
#define TOT_BLOCKS  (FWD_BLOCKS + GOLD_BLOCKS)

typedef unsigned long long ull;

__device__ __align__(16) float g_EpT[NN * NN];   // exp(trans)^T : [j][i]
__device__ double   g_logZ;
__device__ double   g_gold;
__device__ unsigned g_done;

__device__ __forceinline__ float ex2f_(float x) {
    float y; asm("ex2.approx.ftz.f32 %0, %1;" : "=f"(y) : "f"(x)); return y;
}
__device__ __forceinline__ float lg2f_(float x) {
    float y; asm("lg2.approx.ftz.f32 %0, %1;" : "=f"(y) : "f"(x)); return y;
}
__device__ __forceinline__ void fma2_(ull& d, ull a, ull b) {
    asm("fma.rn.f32x2 %0, %1, %2, %0;" : "+l"(d) : "l"(a), "l"(b));
}
__device__ __forceinline__ ull add2_(ull a, ull b) {
    ull d; asm("add.rn.f32x2 %0, %1, %2;" : "=l"(d) : "l"(a), "l"(b));
    return d;
}
__device__ __forceinline__ float pairsum_(ull a) {
    unsigned lo, hi;
    asm("mov.b64 {%0, %1}, %2;" : "=r"(lo), "=r"(hi) : "l"(a));
    return __uint_as_float(lo) + __uint_as_float(hi);
}

// mask dtype: 0=int32, 1=float32, 2=byte  (row t=0 all-true since lengths>=1)
__device__ __forceinline__ int mask_kind(const void* maskp) {
    unsigned w0 = ((const unsigned*)maskp)[0];
    return (w0 == 1u) ? 0 : (w0 == 0x3F800000u ? 1 : 2);
}
__device__ __forceinline__ bool mask_at(const void* maskp, int kind, int idx) {
    if (kind == 0) return ((const int*)maskp)[idx] != 0;
    if (kind == 1) return ((const float*)maskp)[idx] != 0.0f;
    return ((const unsigned char*)maskp)[idx] != 0;
}

// ---------------- init: exp(trans)^T + zero accumulators --------------------
__global__ void k_init(const float* __restrict__ trans) {
    int tid = blockIdx.x * blockDim.x + threadIdx.x;
    if (tid < NN * NN) {
        int i = tid & (NN - 1);
        int j = tid >> 6;
        g_EpT[tid] = ex2f_(LOG2E * trans[i * NN + j]);
    }
    if (tid == 0) { g_logZ = 0.0; g_gold = 0.0; g_done = 0u; }
}

// ---------------- fused forward + gold + final ------------------------------
__global__ void __launch_bounds__(64, 1)
k_main(const float* __restrict__ emit,
       const float* __restrict__ trans,
       const float* __restrict__ strans,
       const float* __restrict__ etrans,
       const int*   __restrict__ target,
       const void*  __restrict__ maskp,
       float*       __restrict__ out) {
    __shared__ __align__(16) float pbuf[2][NN];   // p vector, double-buffered
    __shared__ float sslot[2];                    // j=0 raw sum (scale source)
    __shared__ float red[4];                      // misc broadcast/reduce slots

    const int tid = threadIdx.x;

    if (blockIdx.x < FWD_BLOCKS) {
        const int w = tid >> 5;
        const int l = tid & 31;
        const int j = tid;                // lane owns output column j = 32w + l
        const int b = blockIdx.x;

        // chain length from prefix mask (block-cooperative)
        const int kind = mask_kind(maskp);
        int cnt = 0;
#pragma unroll
        for (int k = 0; k < 8; ++k)
            cnt += mask_at(maskp, kind, (tid + 64 * k) * BB + b) ? 1 : 0;
        cnt = __reduce_add_sync(0xffffffffu, cnt);
        if (l == 0) red[w] = (float)cnt;
        __syncthreads();
        const int len = (int)red[0] + (int)red[1];

        // E column j, i-pair packed: 32 x f32x2 registers
        ull E[32];
        {
            const ull* ep = (const ull*)(g_EpT + j * NN);
#pragma unroll
            for (int k = 0; k < 32; ++k) E[k] = ep[k];
        }

        const float* eb = emit + (size_t)b * NN + j;

        // init alpha (log2 units), uniform offset M0 = A_{j=0}
        float A = LOG2E * (eb[0] + strans[j]);
        if (tid == 0) red[2] = A;
        __syncthreads();
        const float M0 = red[2];
        float PF = ex2f_(A - M0);
        float mlog = M0;
        float u = 1.0f, dcur = 0.0f;

        pbuf[1][j] = PF;                  // buffer read by step t=1
        __syncthreads();

        // raw emit ring, depth 4: load now, convert 4 bodies later
        float r0, r1, r2, r3;
#define LOADR(var, tt) { int tc = (tt) < len ? (tt) : (len - 1);              \
        var = eb[(size_t)tc * STRIDE_F]; }
        LOADR(r0, 1) LOADR(r1, 2) LOADR(r2, 3) LOADR(r3, 4)

        int t = 1;
#define BODY(RR, BI, BO) {                                                    \
        mlog += dcur;                                                         \
        float g = ex2f_(LOG2E * RR);      /* RR loaded 4 bodies ago */        \
        { int tc = (t + 4) < len ? (t + 4) : (len - 1);                       \
          RR = eb[(size_t)tc * STRIDE_F]; }                                   \
        const ulonglong2* pb = (const ulonglong2*)pbuf[BI];                   \
        ull a0 = 0, a1 = 0, a2 = 0, a3 = 0;                                   \
        _Pragma("unroll")                                                     \
        for (int m = 0; m < 16; m += 2) {                                     \
            ulonglong2 q = pb[m];                                             \
            ulonglong2 r = pb[m + 1];                                         \
            fma2_(a0, q.x, E[2 * m]);     fma2_(a1, q.y, E[2 * m + 1]);       \
            fma2_(a2, r.x, E[2 * m + 2]); fma2_(a3, r.y, E[2 * m + 3]);       \
        }                                                                     \
        float s = pairsum_(add2_(add2_(a0, a1), add2_(a2, a3)));              \
        float pn = s * (g * u);                                               \
        pbuf[BO][j] = pn;                                                     \
        if (j == 0) sslot[BO] = s;                                            \
        __syncthreads();                                                      \
        float v0 = sslot[BO];             /* consumed late next step */       \
        int ex = (int)((__float_as_uint(v0) >> 23) & 0xFF);                   \
        int d = ex - 127;                                                     \
        if (ex == 0 || ex == 255) d = 0;                                      \
        if (d > 120) d = 120; if (d < -120) d = -120;                         \
        u = __uint_as_float((unsigned)(127 - d) << 23);                       \
        dcur = (float)d;                                                      \
        PF = pn;                                                              \
        ++t; }

        while (t + 3 < len) {             // t ≡ 1 (mod 4) at loop head
            BODY(r0, 1, 0)
            BODY(r1, 0, 1)
            BODY(r2, 1, 0)
            BODY(r3, 0, 1)
        }
        while (t < len) {                 // ≤3 remainder steps
            float rr = eb[(size_t)t * STRIDE_F];
            int bi = t & 1, bo = bi ^ 1;
            mlog += dcur;
            float g = ex2f_(LOG2E * rr);
            const ulonglong2* pb = (const ulonglong2*)pbuf[bi];
            ull a0 = 0, a1 = 0, a2 = 0, a3 = 0;
#pragma unroll
            for (int m = 0; m < 16; m += 2) {
                ulonglong2 q = pb[m];
                ulonglong2 r = pb[m + 1];
                fma2_(a0, q.x, E[2 * m]);     fma2_(a1, q.y, E[2 * m + 1]);
                fma2_(a2, r.x, E[2 * m + 2]); fma2_(a3, r.y, E[2 * m + 3]);
            }
            float s = pairsum_(add2_(add2_(a0, a1), add2_(a2, a3)));
            float pn = s * (g * u);
            pbuf[bo][j] = pn;
            if (j == 0) sslot[bo] = s;
            __syncthreads();
            float v0 = sslot[bo];
            int ex = (int)((__float_as_uint(v0) >> 23) & 0xFF);
            int d = ex - 127;
            if (ex == 0 || ex == 255) d = 0;
            if (d > 120) d = 120; if (d < -120) d = -120;
            u = __uint_as_float((unsigned)(127 - d) << 23);
            dcur = (float)d;
            PF = pn;
            ++t;
        }

        // logZ_b = ln LSE_j(alpha_j + etrans_j),  alpha(log2) = lg2(PF)+mlog
        float G = lg2f_(PF) + mlog + LOG2E * etrans[j];
        float m2 = G;
#pragma unroll
        for (int o = 16; o; o >>= 1) m2 = fmaxf(m2, __shfl_xor_sync(0xffffffffu, m2, o));
        float s = ex2f_(G - m2);
#pragma unroll
        for (int o = 16; o; o >>= 1) s += __shfl_xor_sync(0xffffffffu, s, o);
        __syncthreads();                  // red[] reuse
        if (l == 0) { red[w] = m2; red[2 + w] = s; }
        __syncthreads();
        if (tid == 0) {
            float ma = fmaxf(red[0], red[1]);
            float ss = red[2] * ex2f_(red[0] - ma) + red[3] * ex2f_(red[1] - ma);
            atomicAdd(&g_logZ, (double)(LN2F * (ma + lg2f_(ss))));
        }
    } else {
        // ======== gold path score ========
        int idx = (blockIdx.x - FWD_BLOCKS) * 64 + tid;   // = t*BB + b
        int t = idx >> 9;
        int kind = mask_kind(maskp);
        float c = 0.0f;
        if (mask_at(maskp, kind, idx)) {
            int tg = target[idx];
            c = emit[(size_t)idx * NN + tg];
            if (t > 0) c += trans[target[idx - BB] * NN + tg];
            else       c += strans[tg];
            bool mnext = (t < TT - 1) && mask_at(maskp, kind, idx + BB);
            if (!mnext) c += etrans[tg];
        }
#pragma unroll
        for (int o = 16; o; o >>= 1) c += __shfl_xor_sync(0xffffffffu, c, o);
        if ((tid & 31) == 0) atomicAdd(&g_gold, (double)c);
    }

    // ======== last block writes the result ========
    __syncthreads();
    if (tid == 0) {
        __threadfence();
        if (atomicAdd(&g_done, 1u) == TOT_BLOCKS - 1) {
            double lz = atomicAdd(&g_logZ, 0.0);
            double gd = atomicAdd(&g_gold, 0.0);
            out[0] = (float)(lz - gd);
        }
    }
}

extern "C" void kernel_launch(void* const* d_in, const int* in_sizes, int n_in,
                              void* d_out, int out_size) {
    const float* emit   = (const float*)d_in[0];
    const float* trans  = (const float*)d_in[1];
    const float* strans = (const float*)d_in[2];
    const float* etrans = (const float*)d_in[3];
    const int*   target = (const int*)d_in[4];
    const void*  mask   = d_in[5];
    (void)in_sizes; (void)n_in; (void)out_size;

    k_init<<<16, 256>>>(trans);
    k_main<<<TOT_BLOCKS, 64>>>(emit, trans, strans, etrans, target, mask,
                               (float*)d_out);
}